// round 1
// baseline (speedup 1.0000x reference)
#include <cuda_runtime.h>
#include <math.h>

// ---------------------------------------------------------------------------
// Problem constants
// ---------------------------------------------------------------------------
#define Bz   2
#define Cc   256
#define NH   8
#define HD   32
#define NN   4096          // H*W
#define GR   8             // groups
#define CPG  32            // channels per group
#define EPSV 1e-5f

// ---------------------------------------------------------------------------
// Scratch (device globals — no allocation allowed)
// ---------------------------------------------------------------------------
__device__ float g_psum[128];
__device__ float g_psq[128];
__device__ float g_mean[16];
__device__ float g_rstd[16];
__device__ float g_q[Bz * NH * NN * HD];   // [b][h][n][d]
__device__ float g_k[Bz * NH * NN * HD];
__device__ float g_v[Bz * NH * NN * HD];
__device__ float g_o[Bz * Cc * NN];        // [b][c][n]  (attn output, pre-proj)

// ---------------------------------------------------------------------------
// Kernel 1a: partial GroupNorm stats. 128 blocks: bg = blockIdx.x>>3, 8 parts.
// Each (b,g) group is a contiguous 32*4096-float slab of x.
// ---------------------------------------------------------------------------
__global__ __launch_bounds__(256) void gn_stats_partial(const float* __restrict__ x) {
    int blk  = blockIdx.x;              // 0..127
    int bg   = blk >> 3;
    int part = blk & 7;
    const float4* p4 = (const float4*)(x + (size_t)bg * CPG * NN + (size_t)part * (CPG * NN / 8));
    const int n4 = (CPG * NN / 8) / 4;  // 4096 float4s
    float s = 0.f, sq = 0.f;
    for (int i = threadIdx.x; i < n4; i += 256) {
        float4 v = p4[i];
        s  += v.x + v.y + v.z + v.w;
        sq += v.x * v.x + v.y * v.y + v.z * v.z + v.w * v.w;
    }
    __shared__ float ss[8], ssq[8];
    for (int o = 16; o; o >>= 1) {
        s  += __shfl_xor_sync(0xffffffffu, s,  o);
        sq += __shfl_xor_sync(0xffffffffu, sq, o);
    }
    if ((threadIdx.x & 31) == 0) { ss[threadIdx.x >> 5] = s; ssq[threadIdx.x >> 5] = sq; }
    __syncthreads();
    if (threadIdx.x == 0) {
        float S = 0.f, SQ = 0.f;
        for (int i = 0; i < 8; i++) { S += ss[i]; SQ += ssq[i]; }
        g_psum[blk] = S;
        g_psq[blk]  = SQ;
    }
}

// Kernel 1b: finalize stats. 1 block, 16 threads.
__global__ void gn_stats_final() {
    int bg = threadIdx.x;
    if (bg >= 16) return;
    float S = 0.f, SQ = 0.f;
    for (int i = 0; i < 8; i++) { S += g_psum[bg * 8 + i]; SQ += g_psq[bg * 8 + i]; }
    const float inv = 1.0f / (float)(CPG * NN);
    float mean = S * inv;
    float var  = SQ * inv - mean * mean;
    g_mean[bg] = mean;
    g_rstd[bg] = rsqrtf(var + EPSV);
}

// ---------------------------------------------------------------------------
// Kernel 2: QKV GEMM, GroupNorm fused on B-operand load.
//   out[b][o][n] = sum_c W[o][c] * hn[b][c][n] + bias[o]
//   scattered into g_q/g_k/g_v as [b][h][n][d].
// Tiles: BM=128 (o), BN=64 (n), BK=32. 256 threads, 8x4 micro-tile.
// ---------------------------------------------------------------------------
__global__ __launch_bounds__(256) void qkv_gemm_kernel(
    const float* __restrict__ x, const float* __restrict__ gnw,
    const float* __restrict__ gnb, const float* __restrict__ W,
    const float* __restrict__ bias) {
    __shared__ float As[32][132];
    __shared__ float Bs[32][68];
    const int b  = blockIdx.z;
    const int o0 = blockIdx.y * 128;
    const int n0 = blockIdx.x * 64;
    const int tid = threadIdx.x;
    const int tx = tid & 15, ty = tid >> 4;

    float acc[8][4];
#pragma unroll
    for (int i = 0; i < 8; i++)
#pragma unroll
        for (int j = 0; j < 4; j++) acc[i][j] = 0.f;

    const int kk = tid & 31;
    const int mb = tid >> 5;        // 0..7
    const int nB = tid & 63;
    const int kb = tid >> 6;        // 0..3

    for (int k0 = 0; k0 < Cc; k0 += 32) {
        __syncthreads();
        // A tile: As[kk][m] = W[(o0+m)*C + k0+kk]
#pragma unroll
        for (int i = 0; i < 16; i++) {
            int m = mb + 8 * i;
            As[kk][m] = W[(size_t)(o0 + m) * Cc + k0 + kk];
        }
        // B tile with GroupNorm fused (whole BK slice is one group)
        const float mu = g_mean[b * 8 + (k0 >> 5)];
        const float rs = g_rstd[b * 8 + (k0 >> 5)];
#pragma unroll
        for (int i = 0; i < 8; i++) {
            int kr = kb + 4 * i;
            int c  = k0 + kr;
            float v = x[((size_t)b * Cc + c) * NN + n0 + nB];
            Bs[kr][nB] = (v - mu) * rs * gnw[c] + gnb[c];
        }
        __syncthreads();
#pragma unroll 8
        for (int kd = 0; kd < 32; kd++) {
            float4 a0 = *(const float4*)&As[kd][ty * 8];
            float4 a1 = *(const float4*)&As[kd][ty * 8 + 4];
            float4 b4 = *(const float4*)&Bs[kd][tx * 4];
            float av[8] = {a0.x, a0.y, a0.z, a0.w, a1.x, a1.y, a1.z, a1.w};
            float bv[4] = {b4.x, b4.y, b4.z, b4.w};
#pragma unroll
            for (int i = 0; i < 8; i++)
#pragma unroll
                for (int j = 0; j < 4; j++) acc[i][j] += av[i] * bv[j];
        }
    }

    // Epilogue: o rows o0+ty*8 .. +7 are 8 consecutive channels -> 8 consecutive d
    // within one head of one of q/k/v. Vectorize d-contiguous stores.
    const int obase = o0 + ty * 8;
    const int which = obase >> 8;          // 0=q 1=k 2=v (tile never crosses)
    const int rem   = obase & 255;
    const int h     = rem >> 5;
    const int d0    = rem & 31;            // multiple of 8
    float* dst = (which == 0) ? g_q : (which == 1 ? g_k : g_v);
    float bi[8];
#pragma unroll
    for (int i = 0; i < 8; i++) bi[i] = bias[obase + i];
#pragma unroll
    for (int j = 0; j < 4; j++) {
        int n = n0 + tx * 4 + j;
        float* p = dst + (((size_t)b * NH + h) * NN + n) * HD + d0;
        float4 w0 = make_float4(acc[0][j] + bi[0], acc[1][j] + bi[1],
                                acc[2][j] + bi[2], acc[3][j] + bi[3]);
        float4 w1 = make_float4(acc[4][j] + bi[4], acc[5][j] + bi[5],
                                acc[6][j] + bi[6], acc[7][j] + bi[7]);
        *(float4*)p       = w0;
        *(float4*)(p + 4) = w1;
    }
}

// ---------------------------------------------------------------------------
// Kernel 3: flash attention, fp32.
// Grid: (N/128, NH, B). 256 threads (16x16). BM=128 queries, BN=64 keys/tile.
// Thread (ty,tx): S rows ty*8..+7, S cols tx*4..+3.
// PV stage: rows ty*8..+7, dims (tx&7)*4..+3, k-half (tx>>3); halves combined
// by shfl_xor(8) at the end.
// ---------------------------------------------------------------------------
#define QT_LD 132
#define KT_LD 68
#define VS_LD 36
#define PT_LD 132
#define ATTN_SMEM ((32 * QT_LD + 32 * KT_LD + 64 * VS_LD + 64 * PT_LD) * 4)

__global__ __launch_bounds__(256) void attn_kernel() {
    extern __shared__ float sm[];
    float* Qt = sm;                        // [32][132]  Qt[d][r] (pre-scaled)
    float* Kt = Qt + 32 * QT_LD;           // [32][68]   Kt[d][c]
    float* Vs = Kt + 32 * KT_LD;           // [64][36]   Vs[c][d]
    float* Pt = Vs + 64 * VS_LD;           // [64][132]  Pt[c][r]

    const int b  = blockIdx.z;
    const int h  = blockIdx.y;
    const int q0 = blockIdx.x * 128;
    const int tid = threadIdx.x;
    const int tx = tid & 15, ty = tid >> 4;
    const int khalf = tx >> 3, dg = tx & 7;
    const float scale = 0.1767766952966369f;  // 1/sqrt(32)

    const size_t bh = (size_t)b * NH + h;
    const float* qg = g_q + (bh * NN + q0) * HD;

    // Load Q tile (transposed, pre-scaled)
    {
        const int dcol = (tid & 7) * 4;
        const int r0 = tid >> 3;
#pragma unroll
        for (int it = 0; it < 4; it++) {
            int r = r0 + 32 * it;
            float4 v = *(const float4*)&qg[(size_t)r * HD + dcol];
            Qt[(dcol + 0) * QT_LD + r] = v.x * scale;
            Qt[(dcol + 1) * QT_LD + r] = v.y * scale;
            Qt[(dcol + 2) * QT_LD + r] = v.z * scale;
            Qt[(dcol + 3) * QT_LD + r] = v.w * scale;
        }
    }

    float m[8], l[8], acc[8][4];
#pragma unroll
    for (int i = 0; i < 8; i++) {
        m[i] = -1e30f; l[i] = 0.f;
#pragma unroll
        for (int j = 0; j < 4; j++) acc[i][j] = 0.f;
    }

    for (int kt = 0; kt < NN / 64; kt++) {
        const int k0 = kt * 64;
        __syncthreads();   // prev-iter PV reads of Vs/Pt done
        // Load K (transposed) and V tiles
        {
            const float* kg = g_k + (bh * NN + k0) * HD;
            const float* vg = g_v + (bh * NN + k0) * HD;
            const int dcol = (tid & 7) * 4;
            const int c0 = tid >> 3;
#pragma unroll
            for (int it = 0; it < 2; it++) {
                int c = c0 + 32 * it;
                float4 kv = *(const float4*)&kg[(size_t)c * HD + dcol];
                Kt[(dcol + 0) * KT_LD + c] = kv.x;
                Kt[(dcol + 1) * KT_LD + c] = kv.y;
                Kt[(dcol + 2) * KT_LD + c] = kv.z;
                Kt[(dcol + 3) * KT_LD + c] = kv.w;
                float4 vv = *(const float4*)&vg[(size_t)c * HD + dcol];
                *(float4*)&Vs[c * VS_LD + dcol] = vv;
            }
        }
        __syncthreads();

        // S = (Q*scale) @ K^T   (8x4 per thread)
        float s[8][4];
#pragma unroll
        for (int i = 0; i < 8; i++)
#pragma unroll
            for (int j = 0; j < 4; j++) s[i][j] = 0.f;
#pragma unroll 8
        for (int kd = 0; kd < 32; kd++) {
            float4 a0 = *(const float4*)&Qt[kd * QT_LD + ty * 8];
            float4 a1 = *(const float4*)&Qt[kd * QT_LD + ty * 8 + 4];
            float4 b4 = *(const float4*)&Kt[kd * KT_LD + tx * 4];
            float av[8] = {a0.x, a0.y, a0.z, a0.w, a1.x, a1.y, a1.z, a1.w};
            float bv[4] = {b4.x, b4.y, b4.z, b4.w};
#pragma unroll
            for (int i = 0; i < 8; i++)
#pragma unroll
                for (int j = 0; j < 4; j++) s[i][j] += av[i] * bv[j];
        }

        // Online softmax update (row groups = 16 lanes within half-warp)
#pragma unroll
        for (int i = 0; i < 8; i++) {
            float rm = fmaxf(fmaxf(s[i][0], s[i][1]), fmaxf(s[i][2], s[i][3]));
#pragma unroll
            for (int o = 8; o; o >>= 1)
                rm = fmaxf(rm, __shfl_xor_sync(0xffffffffu, rm, o));
            float mn = fmaxf(m[i], rm);
            float corr = __expf(m[i] - mn);
            float rs = 0.f;
#pragma unroll
            for (int j = 0; j < 4; j++) {
                s[i][j] = __expf(s[i][j] - mn);
                rs += s[i][j];
            }
#pragma unroll
            for (int o = 8; o; o >>= 1)
                rs += __shfl_xor_sync(0xffffffffu, rs, o);
            l[i] = l[i] * corr + rs;
            m[i] = mn;
#pragma unroll
            for (int j = 0; j < 4; j++) acc[i][j] *= corr;
        }

        // Stage P transposed: Pt[c][r]
#pragma unroll
        for (int j = 0; j < 4; j++) {
            int c = tx * 4 + j;
            *(float4*)&Pt[c * PT_LD + ty * 8] =
                make_float4(s[0][j], s[1][j], s[2][j], s[3][j]);
            *(float4*)&Pt[c * PT_LD + ty * 8 + 4] =
                make_float4(s[4][j], s[5][j], s[6][j], s[7][j]);
        }
        __syncthreads();

        // O += P @ V over this thread's k-half
#pragma unroll 8
        for (int k = 0; k < 32; k++) {
            int kk = khalf * 32 + k;
            float4 a0 = *(const float4*)&Pt[kk * PT_LD + ty * 8];
            float4 a1 = *(const float4*)&Pt[kk * PT_LD + ty * 8 + 4];
            float4 b4 = *(const float4*)&Vs[kk * VS_LD + dg * 4];
            float av[8] = {a0.x, a0.y, a0.z, a0.w, a1.x, a1.y, a1.z, a1.w};
            float bv[4] = {b4.x, b4.y, b4.z, b4.w};
#pragma unroll
            for (int i = 0; i < 8; i++)
#pragma unroll
                for (int j = 0; j < 4; j++) acc[i][j] += av[i] * bv[j];
        }
    }

    // Combine the two k-half partials (lanes tx and tx^8 share rows & dims)
#pragma unroll
    for (int i = 0; i < 8; i++)
#pragma unroll
        for (int j = 0; j < 4; j++)
            acc[i][j] += __shfl_xor_sync(0xffffffffu, acc[i][j], 8);

    if (khalf == 0) {
#pragma unroll
        for (int i = 0; i < 8; i++) {
            float inv = 1.0f / l[i];
            int r = q0 + ty * 8 + i;
#pragma unroll
            for (int j = 0; j < 4; j++) {
                int d = dg * 4 + j;
                g_o[(bh * HD + d) * NN + r] = acc[i][j] * inv;
            }
        }
    }
}

// ---------------------------------------------------------------------------
// Kernel 4: output projection GEMM.
//   out[b][o][n] = sum_c Wp[o][c] * g_o[b][c][n] + bp[o]
// ---------------------------------------------------------------------------
__global__ __launch_bounds__(256) void proj_gemm_kernel(
    const float* __restrict__ W, const float* __restrict__ bias,
    float* __restrict__ out) {
    __shared__ float As[32][132];
    __shared__ float Bs[32][68];
    const int b  = blockIdx.z;
    const int o0 = blockIdx.y * 128;
    const int n0 = blockIdx.x * 64;
    const int tid = threadIdx.x;
    const int tx = tid & 15, ty = tid >> 4;

    float acc[8][4];
#pragma unroll
    for (int i = 0; i < 8; i++)
#pragma unroll
        for (int j = 0; j < 4; j++) acc[i][j] = 0.f;

    const int kk = tid & 31;
    const int mb = tid >> 5;
    const int nB = tid & 63;
    const int kb = tid >> 6;

    for (int k0 = 0; k0 < Cc; k0 += 32) {
        __syncthreads();
#pragma unroll
        for (int i = 0; i < 16; i++) {
            int m = mb + 8 * i;
            As[kk][m] = W[(size_t)(o0 + m) * Cc + k0 + kk];
        }
#pragma unroll
        for (int i = 0; i < 8; i++) {
            int kr = kb + 4 * i;
            Bs[kr][nB] = g_o[((size_t)b * Cc + k0 + kr) * NN + n0 + nB];
        }
        __syncthreads();
#pragma unroll 8
        for (int kd = 0; kd < 32; kd++) {
            float4 a0 = *(const float4*)&As[kd][ty * 8];
            float4 a1 = *(const float4*)&As[kd][ty * 8 + 4];
            float4 b4 = *(const float4*)&Bs[kd][tx * 4];
            float av[8] = {a0.x, a0.y, a0.z, a0.w, a1.x, a1.y, a1.z, a1.w};
            float bv[4] = {b4.x, b4.y, b4.z, b4.w};
#pragma unroll
            for (int i = 0; i < 8; i++)
#pragma unroll
                for (int j = 0; j < 4; j++) acc[i][j] += av[i] * bv[j];
        }
    }
#pragma unroll
    for (int i = 0; i < 8; i++) {
        int o = o0 + ty * 8 + i;
        float bi = bias[o];
        float4 w = make_float4(acc[i][0] + bi, acc[i][1] + bi,
                               acc[i][2] + bi, acc[i][3] + bi);
        *(float4*)&out[((size_t)b * Cc + o) * NN + n0 + tx * 4] = w;
    }
}

// ---------------------------------------------------------------------------
// Launch
// ---------------------------------------------------------------------------
extern "C" void kernel_launch(void* const* d_in, const int* in_sizes, int n_in,
                              void* d_out, int out_size) {
    const float* x    = (const float*)d_in[0];
    const float* gnw  = (const float*)d_in[1];
    const float* gnb  = (const float*)d_in[2];
    const float* wqkv = (const float*)d_in[3];
    const float* bqkv = (const float*)d_in[4];
    const float* wproj= (const float*)d_in[5];
    const float* bproj= (const float*)d_in[6];
    float* out = (float*)d_out;

    cudaFuncSetAttribute(attn_kernel,
                         cudaFuncAttributeMaxDynamicSharedMemorySize, ATTN_SMEM);

    gn_stats_partial<<<128, 256>>>(x);
    gn_stats_final<<<1, 16>>>();

    dim3 gq(NN / 64, (3 * Cc) / 128, Bz);
    qkv_gemm_kernel<<<gq, 256>>>(x, gnw, gnb, wqkv, bqkv);

    dim3 ga(NN / 128, NH, Bz);
    attn_kernel<<<ga, 256, ATTN_SMEM>>>();

    dim3 gp(NN / 64, Cc / 128, Bz);
    proj_gemm_kernel<<<gp, 256>>>(wproj, bproj, out);
}

// round 2
// speedup vs baseline: 2.3107x; 2.3107x over previous
#include <cuda_runtime.h>
#include <math.h>
#include <stdint.h>

// ---------------------------------------------------------------------------
// Problem constants
// ---------------------------------------------------------------------------
#define Bz   2
#define Cc   256
#define NH   8
#define HD   32
#define NN   4096          // H*W
#define GR   8             // groups
#define CPG  32            // channels per group
#define EPSV 1e-5f

// ---------------------------------------------------------------------------
// Scratch (device globals — no allocation allowed)
// ---------------------------------------------------------------------------
__device__ float g_psum[128];
__device__ float g_psq[128];
__device__ float g_mean[16];
__device__ float g_rstd[16];
__device__ float g_q[Bz * NH * NN * HD];   // [b][h][n][d]
__device__ float g_k[Bz * NH * NN * HD];
__device__ float g_v[Bz * NH * NN * HD];
__device__ float g_o[Bz * Cc * NN];        // [b][c][n]  (attn output, pre-proj)

// ---------------------------------------------------------------------------
// tf32 helpers
// ---------------------------------------------------------------------------
__device__ __forceinline__ uint32_t f2tf(float x) {
    uint32_t r;
    asm("cvt.rna.tf32.f32 %0, %1;" : "=r"(r) : "f"(x));
    return r;
}

__device__ __forceinline__ void mma_tf32(float d[4], const uint32_t a[4],
                                         const uint32_t b[2], const float c[4]) {
    asm volatile(
        "mma.sync.aligned.m16n8k8.row.col.f32.tf32.tf32.f32 "
        "{%0,%1,%2,%3}, {%4,%5,%6,%7}, {%8,%9}, {%10,%11,%12,%13};"
        : "=f"(d[0]), "=f"(d[1]), "=f"(d[2]), "=f"(d[3])
        : "r"(a[0]), "r"(a[1]), "r"(a[2]), "r"(a[3]),
          "r"(b[0]), "r"(b[1]),
          "f"(c[0]), "f"(c[1]), "f"(c[2]), "f"(c[3]));
}

// ---------------------------------------------------------------------------
// Kernel 1a: partial GroupNorm stats. 128 blocks.
// ---------------------------------------------------------------------------
__global__ __launch_bounds__(256) void gn_stats_partial(const float* __restrict__ x) {
    int blk  = blockIdx.x;              // 0..127
    int bg   = blk >> 3;
    int part = blk & 7;
    const float4* p4 = (const float4*)(x + (size_t)bg * CPG * NN + (size_t)part * (CPG * NN / 8));
    const int n4 = (CPG * NN / 8) / 4;
    float s = 0.f, sq = 0.f;
    for (int i = threadIdx.x; i < n4; i += 256) {
        float4 v = p4[i];
        s  += v.x + v.y + v.z + v.w;
        sq += v.x * v.x + v.y * v.y + v.z * v.z + v.w * v.w;
    }
    __shared__ float ss[8], ssq[8];
    for (int o = 16; o; o >>= 1) {
        s  += __shfl_xor_sync(0xffffffffu, s,  o);
        sq += __shfl_xor_sync(0xffffffffu, sq, o);
    }
    if ((threadIdx.x & 31) == 0) { ss[threadIdx.x >> 5] = s; ssq[threadIdx.x >> 5] = sq; }
    __syncthreads();
    if (threadIdx.x == 0) {
        float S = 0.f, SQ = 0.f;
        for (int i = 0; i < 8; i++) { S += ss[i]; SQ += ssq[i]; }
        g_psum[blk] = S;
        g_psq[blk]  = SQ;
    }
}

__global__ void gn_stats_final() {
    int bg = threadIdx.x;
    if (bg >= 16) return;
    float S = 0.f, SQ = 0.f;
    for (int i = 0; i < 8; i++) { S += g_psum[bg * 8 + i]; SQ += g_psq[bg * 8 + i]; }
    const float inv = 1.0f / (float)(CPG * NN);
    float mean = S * inv;
    float var  = SQ * inv - mean * mean;
    g_mean[bg] = mean;
    g_rstd[bg] = rsqrtf(var + EPSV);
}

// ---------------------------------------------------------------------------
// Kernel 2: QKV GEMM, GroupNorm fused on B-operand load (scalar fp32).
// ---------------------------------------------------------------------------
__global__ __launch_bounds__(256) void qkv_gemm_kernel(
    const float* __restrict__ x, const float* __restrict__ gnw,
    const float* __restrict__ gnb, const float* __restrict__ W,
    const float* __restrict__ bias) {
    __shared__ float As[32][132];
    __shared__ float Bs[32][68];
    const int b  = blockIdx.z;
    const int o0 = blockIdx.y * 128;
    const int n0 = blockIdx.x * 64;
    const int tid = threadIdx.x;
    const int tx = tid & 15, ty = tid >> 4;

    float acc[8][4];
#pragma unroll
    for (int i = 0; i < 8; i++)
#pragma unroll
        for (int j = 0; j < 4; j++) acc[i][j] = 0.f;

    const int kk = tid & 31;
    const int mb = tid >> 5;
    const int nB = tid & 63;
    const int kb = tid >> 6;

    for (int k0 = 0; k0 < Cc; k0 += 32) {
        __syncthreads();
#pragma unroll
        for (int i = 0; i < 16; i++) {
            int m = mb + 8 * i;
            As[kk][m] = W[(size_t)(o0 + m) * Cc + k0 + kk];
        }
        const float mu = g_mean[b * 8 + (k0 >> 5)];
        const float rs = g_rstd[b * 8 + (k0 >> 5)];
#pragma unroll
        for (int i = 0; i < 8; i++) {
            int kr = kb + 4 * i;
            int c  = k0 + kr;
            float v = x[((size_t)b * Cc + c) * NN + n0 + nB];
            Bs[kr][nB] = (v - mu) * rs * gnw[c] + gnb[c];
        }
        __syncthreads();
#pragma unroll 8
        for (int kd = 0; kd < 32; kd++) {
            float4 a0 = *(const float4*)&As[kd][ty * 8];
            float4 a1 = *(const float4*)&As[kd][ty * 8 + 4];
            float4 b4 = *(const float4*)&Bs[kd][tx * 4];
            float av[8] = {a0.x, a0.y, a0.z, a0.w, a1.x, a1.y, a1.z, a1.w};
            float bv[4] = {b4.x, b4.y, b4.z, b4.w};
#pragma unroll
            for (int i = 0; i < 8; i++)
#pragma unroll
                for (int j = 0; j < 4; j++) acc[i][j] += av[i] * bv[j];
        }
    }

    const int obase = o0 + ty * 8;
    const int which = obase >> 8;          // 0=q 1=k 2=v
    const int rem   = obase & 255;
    const int h     = rem >> 5;
    const int d0    = rem & 31;
    float* dst = (which == 0) ? g_q : (which == 1 ? g_k : g_v);
    float bi[8];
#pragma unroll
    for (int i = 0; i < 8; i++) bi[i] = bias[obase + i];
#pragma unroll
    for (int j = 0; j < 4; j++) {
        int n = n0 + tx * 4 + j;
        float* p = dst + (((size_t)b * NH + h) * NN + n) * HD + d0;
        float4 w0 = make_float4(acc[0][j] + bi[0], acc[1][j] + bi[1],
                                acc[2][j] + bi[2], acc[3][j] + bi[3]);
        float4 w1 = make_float4(acc[4][j] + bi[4], acc[5][j] + bi[5],
                                acc[6][j] + bi[6], acc[7][j] + bi[7]);
        *(float4*)p       = w0;
        *(float4*)(p + 4) = w1;
    }
}

// ---------------------------------------------------------------------------
// Kernel 3: flash attention with tf32 tensor-core mma.
// Grid: (N/128, NH, B). 256 threads = 8 warps. Each warp: 16 query rows.
// Key tile BN=64. Q frags register-resident for whole kernel.
// K staged transposed in smem (ld=72: conflict-free B-frag reads);
// V staged [key][dim] (ld=40: conflict-free).
// P (C-frag layout) converted to A-frag layout via intra-quad shuffles.
// ---------------------------------------------------------------------------
__global__ __launch_bounds__(256) void attn_tc_kernel() {
    __shared__ uint32_t Kt[32][72];   // Kt[dim][key]
    __shared__ uint32_t Vs[64][40];   // Vs[key][dim]

    const int b  = blockIdx.z;
    const int h  = blockIdx.y;
    const int q0 = blockIdx.x * 128;
    const int tid = threadIdx.x;
    const int wid = tid >> 5, lane = tid & 31;
    const int r = lane >> 2, q = lane & 3;
    const size_t bh = (size_t)b * NH + h;
    const float scale = 0.1767766952966369f;  // 1/sqrt(32)

    // ---- Q fragments (pre-scaled, tf32), resident all kernel ----
    uint32_t qa[4][4];
    {
        const float* qg = g_q + (bh * NN + q0 + (size_t)wid * 16) * HD;
#pragma unroll
        for (int kt = 0; kt < 4; kt++) {
            qa[kt][0] = f2tf(qg[(size_t)r       * HD + kt * 8 + q]     * scale);
            qa[kt][1] = f2tf(qg[(size_t)(r + 8) * HD + kt * 8 + q]     * scale);
            qa[kt][2] = f2tf(qg[(size_t)r       * HD + kt * 8 + q + 4] * scale);
            qa[kt][3] = f2tf(qg[(size_t)(r + 8) * HD + kt * 8 + q + 4] * scale);
        }
    }

    float o[4][4];
#pragma unroll
    for (int i = 0; i < 4; i++)
#pragma unroll
        for (int j = 0; j < 4; j++) o[i][j] = 0.f;
    float m0 = -1e30f, m1 = -1e30f, l0 = 0.f, l1 = 0.f;

    // ---- K/V prefetch (software pipeline, regs -> smem) ----
    const int key_ld = tid >> 2;        // 0..63
    const int d0     = (tid & 3) * 8;   // dims handled by this thread
    const float* kg = g_k + bh * NN * HD;
    const float* vg = g_v + bh * NN * HD;

    float4 kr0 = *(const float4*)&kg[(size_t)key_ld * HD + d0];
    float4 kr1 = *(const float4*)&kg[(size_t)key_ld * HD + d0 + 4];
    float4 vr0 = *(const float4*)&vg[(size_t)key_ld * HD + d0];
    float4 vr1 = *(const float4*)&vg[(size_t)key_ld * HD + d0 + 4];

    const int srcA = (lane & ~3) | (q >> 1);
    const int srcC = srcA + 2;

#pragma unroll 1
    for (int t = 0; t < NN / 64; t++) {
        __syncthreads();   // previous tile's smem reads complete
        // stage regs -> smem with tf32 rounding
        Kt[d0 + 0][key_ld] = f2tf(kr0.x);
        Kt[d0 + 1][key_ld] = f2tf(kr0.y);
        Kt[d0 + 2][key_ld] = f2tf(kr0.z);
        Kt[d0 + 3][key_ld] = f2tf(kr0.w);
        Kt[d0 + 4][key_ld] = f2tf(kr1.x);
        Kt[d0 + 5][key_ld] = f2tf(kr1.y);
        Kt[d0 + 6][key_ld] = f2tf(kr1.z);
        Kt[d0 + 7][key_ld] = f2tf(kr1.w);
        Vs[key_ld][d0 + 0] = f2tf(vr0.x);
        Vs[key_ld][d0 + 1] = f2tf(vr0.y);
        Vs[key_ld][d0 + 2] = f2tf(vr0.z);
        Vs[key_ld][d0 + 3] = f2tf(vr0.w);
        Vs[key_ld][d0 + 4] = f2tf(vr1.x);
        Vs[key_ld][d0 + 5] = f2tf(vr1.y);
        Vs[key_ld][d0 + 6] = f2tf(vr1.z);
        Vs[key_ld][d0 + 7] = f2tf(vr1.w);
        __syncthreads();

        // prefetch next tile
        if (t + 1 < NN / 64) {
            const float* kg2 = kg + (size_t)(t + 1) * 64 * HD;
            const float* vg2 = vg + (size_t)(t + 1) * 64 * HD;
            kr0 = *(const float4*)&kg2[(size_t)key_ld * HD + d0];
            kr1 = *(const float4*)&kg2[(size_t)key_ld * HD + d0 + 4];
            vr0 = *(const float4*)&vg2[(size_t)key_ld * HD + d0];
            vr1 = *(const float4*)&vg2[(size_t)key_ld * HD + d0 + 4];
        }

        // ---- S = (Q*scale) @ K^T : 8 n-tiles of m16n8 ----
        float s[8][4];
#pragma unroll
        for (int nt = 0; nt < 8; nt++) {
            s[nt][0] = s[nt][1] = s[nt][2] = s[nt][3] = 0.f;
#pragma unroll
            for (int kt = 0; kt < 4; kt++) {
                uint32_t bf[2];
                bf[0] = Kt[kt * 8 + q][nt * 8 + r];
                bf[1] = Kt[kt * 8 + q + 4][nt * 8 + r];
                mma_tf32(s[nt], qa[kt], bf, s[nt]);
            }
        }

        // ---- online softmax ----
        float rm0 = -1e30f, rm1 = -1e30f;
#pragma unroll
        for (int nt = 0; nt < 8; nt++) {
            rm0 = fmaxf(rm0, fmaxf(s[nt][0], s[nt][1]));
            rm1 = fmaxf(rm1, fmaxf(s[nt][2], s[nt][3]));
        }
        rm0 = fmaxf(rm0, __shfl_xor_sync(0xffffffffu, rm0, 1));
        rm0 = fmaxf(rm0, __shfl_xor_sync(0xffffffffu, rm0, 2));
        rm1 = fmaxf(rm1, __shfl_xor_sync(0xffffffffu, rm1, 1));
        rm1 = fmaxf(rm1, __shfl_xor_sync(0xffffffffu, rm1, 2));
        float mn0 = fmaxf(m0, rm0), mn1 = fmaxf(m1, rm1);
        float corr0 = __expf(m0 - mn0), corr1 = __expf(m1 - mn1);
        m0 = mn0; m1 = mn1;
        float rs0 = 0.f, rs1 = 0.f;
#pragma unroll
        for (int nt = 0; nt < 8; nt++) {
            s[nt][0] = __expf(s[nt][0] - mn0); rs0 += s[nt][0];
            s[nt][1] = __expf(s[nt][1] - mn0); rs0 += s[nt][1];
            s[nt][2] = __expf(s[nt][2] - mn1); rs1 += s[nt][2];
            s[nt][3] = __expf(s[nt][3] - mn1); rs1 += s[nt][3];
        }
        rs0 += __shfl_xor_sync(0xffffffffu, rs0, 1);
        rs0 += __shfl_xor_sync(0xffffffffu, rs0, 2);
        rs1 += __shfl_xor_sync(0xffffffffu, rs1, 1);
        rs1 += __shfl_xor_sync(0xffffffffu, rs1, 2);
        l0 = l0 * corr0 + rs0;
        l1 = l1 * corr1 + rs1;
#pragma unroll
        for (int nt = 0; nt < 4; nt++) {
            o[nt][0] *= corr0; o[nt][1] *= corr0;
            o[nt][2] *= corr1; o[nt][3] *= corr1;
        }

        // ---- O += P @ V : convert P C-frags to A-frags via quad shuffles ----
#pragma unroll
        for (int kc = 0; kc < 8; kc++) {
            float x0 = __shfl_sync(0xffffffffu, s[kc][0], srcA);
            float x1 = __shfl_sync(0xffffffffu, s[kc][1], srcA);
            float x2 = __shfl_sync(0xffffffffu, s[kc][2], srcA);
            float x3 = __shfl_sync(0xffffffffu, s[kc][3], srcA);
            float y0 = __shfl_sync(0xffffffffu, s[kc][0], srcC);
            float y1 = __shfl_sync(0xffffffffu, s[kc][1], srcC);
            float y2 = __shfl_sync(0xffffffffu, s[kc][2], srcC);
            float y3 = __shfl_sync(0xffffffffu, s[kc][3], srcC);
            uint32_t pa[4];
            pa[0] = f2tf((q & 1) ? x1 : x0);   // P(r,   kc*8+q)
            pa[1] = f2tf((q & 1) ? x3 : x2);   // P(r+8, kc*8+q)
            pa[2] = f2tf((q & 1) ? y1 : y0);   // P(r,   kc*8+q+4)
            pa[3] = f2tf((q & 1) ? y3 : y2);   // P(r+8, kc*8+q+4)
#pragma unroll
            for (int nt = 0; nt < 4; nt++) {
                uint32_t bf[2];
                bf[0] = Vs[kc * 8 + q][nt * 8 + r];
                bf[1] = Vs[kc * 8 + q + 4][nt * 8 + r];
                mma_tf32(o[nt], pa, bf, o[nt]);
            }
        }
    }

    // ---- epilogue: O /= l, write [b][c][n] for proj GEMM ----
    float inv0 = 1.0f / l0, inv1 = 1.0f / l1;
    const int gr0 = q0 + wid * 16 + r;
    const int gr1 = gr0 + 8;
#pragma unroll
    for (int nt = 0; nt < 4; nt++) {
        int d = nt * 8 + 2 * q;
        float* base = g_o + (bh * HD + d) * NN;
        base[gr0]      = o[nt][0] * inv0;
        base[NN + gr0] = o[nt][1] * inv0;
        base[gr1]      = o[nt][2] * inv1;
        base[NN + gr1] = o[nt][3] * inv1;
    }
}

// ---------------------------------------------------------------------------
// Kernel 4: output projection GEMM (scalar fp32).
// ---------------------------------------------------------------------------
__global__ __launch_bounds__(256) void proj_gemm_kernel(
    const float* __restrict__ W, const float* __restrict__ bias,
    float* __restrict__ out) {
    __shared__ float As[32][132];
    __shared__ float Bs[32][68];
    const int b  = blockIdx.z;
    const int o0 = blockIdx.y * 128;
    const int n0 = blockIdx.x * 64;
    const int tid = threadIdx.x;
    const int tx = tid & 15, ty = tid >> 4;

    float acc[8][4];
#pragma unroll
    for (int i = 0; i < 8; i++)
#pragma unroll
        for (int j = 0; j < 4; j++) acc[i][j] = 0.f;

    const int kk = tid & 31;
    const int mb = tid >> 5;
    const int nB = tid & 63;
    const int kb = tid >> 6;

    for (int k0 = 0; k0 < Cc; k0 += 32) {
        __syncthreads();
#pragma unroll
        for (int i = 0; i < 16; i++) {
            int m = mb + 8 * i;
            As[kk][m] = W[(size_t)(o0 + m) * Cc + k0 + kk];
        }
#pragma unroll
        for (int i = 0; i < 8; i++) {
            int kr = kb + 4 * i;
            Bs[kr][nB] = g_o[((size_t)b * Cc + k0 + kr) * NN + n0 + nB];
        }
        __syncthreads();
#pragma unroll 8
        for (int kd = 0; kd < 32; kd++) {
            float4 a0 = *(const float4*)&As[kd][ty * 8];
            float4 a1 = *(const float4*)&As[kd][ty * 8 + 4];
            float4 b4 = *(const float4*)&Bs[kd][tx * 4];
            float av[8] = {a0.x, a0.y, a0.z, a0.w, a1.x, a1.y, a1.z, a1.w};
            float bv[4] = {b4.x, b4.y, b4.z, b4.w};
#pragma unroll
            for (int i = 0; i < 8; i++)
#pragma unroll
                for (int j = 0; j < 4; j++) acc[i][j] += av[i] * bv[j];
        }
    }
#pragma unroll
    for (int i = 0; i < 8; i++) {
        int o = o0 + ty * 8 + i;
        float bi = bias[o];
        float4 w = make_float4(acc[i][0] + bi, acc[i][1] + bi,
                               acc[i][2] + bi, acc[i][3] + bi);
        *(float4*)&out[((size_t)b * Cc + o) * NN + n0 + tx * 4] = w;
    }
}

// ---------------------------------------------------------------------------
// Launch
// ---------------------------------------------------------------------------
extern "C" void kernel_launch(void* const* d_in, const int* in_sizes, int n_in,
                              void* d_out, int out_size) {
    const float* x    = (const float*)d_in[0];
    const float* gnw  = (const float*)d_in[1];
    const float* gnb  = (const float*)d_in[2];
    const float* wqkv = (const float*)d_in[3];
    const float* bqkv = (const float*)d_in[4];
    const float* wproj= (const float*)d_in[5];
    const float* bproj= (const float*)d_in[6];
    float* out = (float*)d_out;

    gn_stats_partial<<<128, 256>>>(x);
    gn_stats_final<<<1, 16>>>();

    dim3 gq(NN / 64, (3 * Cc) / 128, Bz);
    qkv_gemm_kernel<<<gq, 256>>>(x, gnw, gnb, wqkv, bqkv);

    dim3 ga(NN / 128, NH, Bz);
    attn_tc_kernel<<<ga, 256>>>();

    dim3 gp(NN / 64, Cc / 128, Bz);
    proj_gemm_kernel<<<gp, 256>>>(wproj, bproj, out);
}

// round 4
// speedup vs baseline: 2.6174x; 1.1328x over previous
#include <cuda_runtime.h>
#include <math.h>
#include <stdint.h>

// ---------------------------------------------------------------------------
// Problem constants
// ---------------------------------------------------------------------------
#define Bz   2
#define Cc   256
#define NH   8
#define HD   32
#define NN   4096
#define CPG  32
#define EPSV 1e-5f
#define LOG2E 1.4426950408889634f

// ---------------------------------------------------------------------------
// Scratch (device globals — no allocation allowed)
// ---------------------------------------------------------------------------
__device__ float g_psum[128];
__device__ float g_psq[128];
__device__ float g_mean[16];
__device__ float g_rstd[16];
__device__ float g_q[Bz * NH * NN * HD];   // [b][h][n][d]
__device__ float g_k[Bz * NH * NN * HD];
__device__ float g_v[Bz * NH * NN * HD];
__device__ float g_o[Bz * Cc * NN];        // [b][c][n]

// ---------------------------------------------------------------------------
// Helpers
// ---------------------------------------------------------------------------
__device__ __forceinline__ uint32_t f2tf(float x) {
    uint32_t r;
    asm("cvt.rna.tf32.f32 %0, %1;" : "=r"(r) : "f"(x));
    return r;
}
__device__ __forceinline__ float ex2f(float x) {
    float r;
    asm("ex2.approx.f32 %0, %1;" : "=f"(r) : "f"(x));
    return r;
}
__device__ __forceinline__ void mma_tf32(float d[4], const uint32_t a[4],
                                         const uint32_t b[2], const float c[4]) {
    asm volatile(
        "mma.sync.aligned.m16n8k8.row.col.f32.tf32.tf32.f32 "
        "{%0,%1,%2,%3}, {%4,%5,%6,%7}, {%8,%9}, {%10,%11,%12,%13};"
        : "=f"(d[0]), "=f"(d[1]), "=f"(d[2]), "=f"(d[3])
        : "r"(a[0]), "r"(a[1]), "r"(a[2]), "r"(a[3]),
          "r"(b[0]), "r"(b[1]),
          "f"(c[0]), "f"(c[1]), "f"(c[2]), "f"(c[3]));
}

// ---------------------------------------------------------------------------
// Kernel 1: GroupNorm stats
// ---------------------------------------------------------------------------
__global__ __launch_bounds__(256) void gn_stats_partial(const float* __restrict__ x) {
    int blk  = blockIdx.x;
    int bg   = blk >> 3;
    int part = blk & 7;
    const float4* p4 = (const float4*)(x + (size_t)bg * CPG * NN + (size_t)part * (CPG * NN / 8));
    const int n4 = (CPG * NN / 8) / 4;
    float s = 0.f, sq = 0.f;
    for (int i = threadIdx.x; i < n4; i += 256) {
        float4 v = p4[i];
        s  += v.x + v.y + v.z + v.w;
        sq += v.x * v.x + v.y * v.y + v.z * v.z + v.w * v.w;
    }
    __shared__ float ss[8], ssq[8];
    for (int o = 16; o; o >>= 1) {
        s  += __shfl_xor_sync(0xffffffffu, s,  o);
        sq += __shfl_xor_sync(0xffffffffu, sq, o);
    }
    if ((threadIdx.x & 31) == 0) { ss[threadIdx.x >> 5] = s; ssq[threadIdx.x >> 5] = sq; }
    __syncthreads();
    if (threadIdx.x == 0) {
        float S = 0.f, SQ = 0.f;
        for (int i = 0; i < 8; i++) { S += ss[i]; SQ += ssq[i]; }
        g_psum[blk] = S;
        g_psq[blk]  = SQ;
    }
}

__global__ void gn_stats_final() {
    int bg = threadIdx.x;
    if (bg >= 16) return;
    float S = 0.f, SQ = 0.f;
    for (int i = 0; i < 8; i++) { S += g_psum[bg * 8 + i]; SQ += g_psq[bg * 8 + i]; }
    const float inv = 1.0f / (float)(CPG * NN);
    float mean = S * inv;
    float var  = SQ * inv - mean * mean;
    g_mean[bg] = mean;
    g_rstd[bg] = rsqrtf(var + EPSV);
}

// ---------------------------------------------------------------------------
// Kernel 2: QKV GEMM (tf32 tensor cores), GroupNorm fused on B load.
// BM=128, BN=128, BK=32. 8 warps (2x4). ld=272 (≡16 mod 32): conflict-free.
// ---------------------------------------------------------------------------
__global__ __launch_bounds__(256, 2) void qkv_tc_kernel(
    const float* __restrict__ x, const float* __restrict__ gnw,
    const float* __restrict__ gnb, const float* __restrict__ W,
    const float* __restrict__ bias) {
    __shared__ __align__(16) uint32_t Ap[4][4][272];
    __shared__ __align__(16) uint32_t Bp[4][4][272];
    const int b  = blockIdx.z;
    const int o0 = blockIdx.y * 128;
    const int n0 = blockIdx.x * 128;
    const int tid = threadIdx.x, wid = tid >> 5, lane = tid & 31;
    const int r = lane >> 2, q = lane & 3;
    const int wr = wid >> 2, wc = wid & 3;

    float acc[4][4][4];
#pragma unroll
    for (int mt = 0; mt < 4; mt++)
#pragma unroll
        for (int nt = 0; nt < 4; nt++)
#pragma unroll
            for (int j = 0; j < 4; j++) acc[mt][nt][j] = 0.f;

    for (int k0 = 0; k0 < Cc; k0 += 32) {
        __syncthreads();
#pragma unroll
        for (int it = 0; it < 4; it++) {
            int idx = tid + 256 * it;
            int row = idx >> 3, c4 = idx & 7;
            float4 w4 = *(const float4*)&W[(size_t)(o0 + row) * Cc + k0 + c4 * 4];
            float wv[4] = {w4.x, w4.y, w4.z, w4.w};
#pragma unroll
            for (int j = 0; j < 4; j++) {
                int k = c4 * 4 + j, i = k & 7;
                Ap[k >> 3][i & 3][2 * row + (i >> 2)] = f2tf(wv[j]);
            }
        }
        const float mu  = g_mean[b * 8 + (k0 >> 5)];
        const float rsd = g_rstd[b * 8 + (k0 >> 5)];
#pragma unroll
        for (int it = 0; it < 16; it++) {
            int idx = tid + 256 * it;
            int c = idx >> 7, n = idx & 127;
            int ch = k0 + c;
            float v = x[((size_t)b * Cc + ch) * NN + n0 + n];
            v = (v - mu) * rsd * gnw[ch] + gnb[ch];
            int i = c & 7;
            Bp[c >> 3][i & 3][2 * n + (i >> 2)] = f2tf(v);
        }
        __syncthreads();

#pragma unroll
        for (int kt = 0; kt < 4; kt++) {
            uint32_t af[4][4];
#pragma unroll
            for (int mt = 0; mt < 4; mt++) {
                int m = wr * 64 + mt * 16;
                uint2 lo = *(const uint2*)&Ap[kt][q][2 * (m + r)];
                uint2 hi = *(const uint2*)&Ap[kt][q][2 * (m + 8 + r)];
                af[mt][0] = lo.x; af[mt][1] = hi.x; af[mt][2] = lo.y; af[mt][3] = hi.y;
            }
            uint2 bfv[4];
#pragma unroll
            for (int nt = 0; nt < 4; nt++)
                bfv[nt] = *(const uint2*)&Bp[kt][q][2 * (wc * 32 + nt * 8 + r)];
#pragma unroll
            for (int mt = 0; mt < 4; mt++)
#pragma unroll
                for (int nt = 0; nt < 4; nt++) {
                    uint32_t bb[2] = {bfv[nt].x, bfv[nt].y};
                    mma_tf32(acc[mt][nt], af[mt], bb, acc[mt][nt]);
                }
        }
    }

#pragma unroll
    for (int mt = 0; mt < 4; mt++) {
        int row0 = o0 + wr * 64 + mt * 16 + r;
        int row1 = row0 + 8;
        float bi0 = bias[row0], bi1 = bias[row1];
        int which = row0 >> 8;
        float* dst = (which == 0) ? g_q : (which == 1 ? g_k : g_v);
        int rem = row0 & 255;
        int hh = rem >> 5;
        int dd0 = rem & 31, dd1 = dd0 + 8;
        float* base = dst + ((size_t)b * NH + hh) * NN * HD;
#pragma unroll
        for (int nt = 0; nt < 4; nt++) {
            int n = n0 + wc * 32 + nt * 8 + 2 * q;
            base[(size_t)n * HD + dd0]       = acc[mt][nt][0] + bi0;
            base[(size_t)(n + 1) * HD + dd0] = acc[mt][nt][1] + bi0;
            base[(size_t)n * HD + dd1]       = acc[mt][nt][2] + bi1;
            base[(size_t)(n + 1) * HD + dd1] = acc[mt][nt][3] + bi1;
        }
    }
}

// ---------------------------------------------------------------------------
// Kernel 3: flash attention, all-tf32 tensor cores, ZERO shuffles in PV.
// Trick: K columns are permuted inside each 8-key group so that smem column
// g*8+2q holds key g*8+q and column g*8+2q+1 holds key g*8+q+4. Then the S
// C-fragment {s0,s1,s2,s3} = {P(r,q),P(r,q+4),P(r+8,q),P(r+8,q+4)} is exactly
// the tf32 A-fragment {a0,a2,a1,a3} for the PV mma over that key group.
// V pair-packed along keys (q,q+4): one LDS64 per PV B-frag, conflict-free.
// ---------------------------------------------------------------------------
__global__ __launch_bounds__(256, 2) void attn_tc_kernel() {
    __shared__ __align__(16) uint32_t Ktp[4][4][144];  // [kt][q][2*col+half] tf32
    __shared__ __align__(16) uint32_t Vtp[8][4][80];   // [grp][q][2*dim+half] tf32

    const int b  = blockIdx.z;
    const int h  = blockIdx.y;
    const int q0 = blockIdx.x * 128;
    const int tid = threadIdx.x, wid = tid >> 5, lane = tid & 31;
    const int r = lane >> 2, q = lane & 3;
    const size_t bh = (size_t)b * NH + h;
    const float sc2 = 0.17677669529663687f * LOG2E;  // 1/sqrt(32) * log2(e)

    // Q fragments (pre-scaled tf32), resident whole kernel
    uint32_t qa[4][4];
    {
        const float* qg = g_q + (bh * NN + q0 + (size_t)wid * 16) * HD;
#pragma unroll
        for (int kt = 0; kt < 4; kt++) {
            qa[kt][0] = f2tf(qg[(size_t)r       * HD + kt * 8 + q]     * sc2);
            qa[kt][1] = f2tf(qg[(size_t)(r + 8) * HD + kt * 8 + q]     * sc2);
            qa[kt][2] = f2tf(qg[(size_t)r       * HD + kt * 8 + q + 4] * sc2);
            qa[kt][3] = f2tf(qg[(size_t)(r + 8) * HD + kt * 8 + q + 4] * sc2);
        }
    }

    float o[4][4];
#pragma unroll
    for (int i = 0; i < 4; i++)
#pragma unroll
        for (int j = 0; j < 4; j++) o[i][j] = 0.f;
    float m0 = -1e30f, m1 = -1e30f, l0 = 0.f, l1 = 0.f;

    // --- producer index maps ---
    // K: thread -> key key_ld (0..63), dims d0..d0+7 (kt group = tid&3)
    const int key_ld = tid >> 2;
    const int d0 = (tid & 3) * 8;
    const int kts = tid & 3;
    const int kkk = key_ld & 7;
    const int pcol = (key_ld & ~7) + ((kkk < 4) ? 2 * kkk : 2 * kkk - 7); // permuted col
    // V: thread -> (grp, qi, dim quad); loads keys grp*8+qi and grp*8+qi+4
    const int vgrp = tid >> 5;
    const int vqi  = (tid >> 3) & 3;
    const int vdq  = tid & 7;

    const float* kg = g_k + bh * NN * HD;
    const float* vg = g_v + bh * NN * HD;
    float4 kr0 = *(const float4*)&kg[(size_t)key_ld * HD + d0];
    float4 kr1 = *(const float4*)&kg[(size_t)key_ld * HD + d0 + 4];
    float4 vr0 = *(const float4*)&vg[(size_t)(vgrp * 8 + vqi)     * HD + vdq * 4];
    float4 vr1 = *(const float4*)&vg[(size_t)(vgrp * 8 + vqi + 4) * HD + vdq * 4];

#pragma unroll 1
    for (int t = 0; t < NN / 64; t++) {
        __syncthreads();
        // stage K (tf32, pairs along dim q/q+4, permuted column)
        {
            float kv[8] = {kr0.x, kr0.y, kr0.z, kr0.w, kr1.x, kr1.y, kr1.z, kr1.w};
#pragma unroll
            for (int i = 0; i < 8; i++)
                Ktp[kts][i & 3][2 * pcol + (i >> 2)] = f2tf(kv[i]);
            // stage V (tf32, pairs along keys q/q+4)
            float v0[4] = {vr0.x, vr0.y, vr0.z, vr0.w};
            float v1[4] = {vr1.x, vr1.y, vr1.z, vr1.w};
#pragma unroll
            for (int j = 0; j < 4; j++) {
                int d = vdq * 4 + j;
                Vtp[vgrp][vqi][2 * d + 0] = f2tf(v0[j]);
                Vtp[vgrp][vqi][2 * d + 1] = f2tf(v1[j]);
            }
        }
        __syncthreads();

        if (t + 1 < NN / 64) {
            const float* kg2 = kg + (size_t)(t + 1) * 64 * HD;
            const float* vg2 = vg + (size_t)(t + 1) * 64 * HD;
            kr0 = *(const float4*)&kg2[(size_t)key_ld * HD + d0];
            kr1 = *(const float4*)&kg2[(size_t)key_ld * HD + d0 + 4];
            vr0 = *(const float4*)&vg2[(size_t)(vgrp * 8 + vqi)     * HD + vdq * 4];
            vr1 = *(const float4*)&vg2[(size_t)(vgrp * 8 + vqi + 4) * HD + vdq * 4];
        }

        // ---- S = Q K^T (tf32); column nt*8+2q holds key nt*8+q etc. ----
        float s[8][4];
#pragma unroll
        for (int nt = 0; nt < 8; nt++) {
            s[nt][0] = s[nt][1] = s[nt][2] = s[nt][3] = 0.f;
#pragma unroll
            for (int kt = 0; kt < 4; kt++) {
                uint2 bf = *(const uint2*)&Ktp[kt][q][2 * (nt * 8 + r)];
                uint32_t bb[2] = {bf.x, bf.y};
                mma_tf32(s[nt], qa[kt], bb, s[nt]);
            }
        }

        // ---- online softmax (base 2); row ops are permutation-invariant ----
        float rm0 = -1e30f, rm1 = -1e30f;
#pragma unroll
        for (int nt = 0; nt < 8; nt++) {
            rm0 = fmaxf(rm0, fmaxf(s[nt][0], s[nt][1]));
            rm1 = fmaxf(rm1, fmaxf(s[nt][2], s[nt][3]));
        }
        rm0 = fmaxf(rm0, __shfl_xor_sync(0xffffffffu, rm0, 1));
        rm0 = fmaxf(rm0, __shfl_xor_sync(0xffffffffu, rm0, 2));
        rm1 = fmaxf(rm1, __shfl_xor_sync(0xffffffffu, rm1, 1));
        rm1 = fmaxf(rm1, __shfl_xor_sync(0xffffffffu, rm1, 2));
        float mn0 = fmaxf(m0, rm0), mn1 = fmaxf(m1, rm1);
        float corr0 = ex2f(m0 - mn0), corr1 = ex2f(m1 - mn1);
        m0 = mn0; m1 = mn1;
        float rs0 = 0.f, rs1 = 0.f;
#pragma unroll
        for (int nt = 0; nt < 8; nt++) {
            s[nt][0] = ex2f(s[nt][0] - mn0); rs0 += s[nt][0];
            s[nt][1] = ex2f(s[nt][1] - mn0); rs0 += s[nt][1];
            s[nt][2] = ex2f(s[nt][2] - mn1); rs1 += s[nt][2];
            s[nt][3] = ex2f(s[nt][3] - mn1); rs1 += s[nt][3];
        }
        rs0 += __shfl_xor_sync(0xffffffffu, rs0, 1);
        rs0 += __shfl_xor_sync(0xffffffffu, rs0, 2);
        rs1 += __shfl_xor_sync(0xffffffffu, rs1, 1);
        rs1 += __shfl_xor_sync(0xffffffffu, rs1, 2);
        l0 = l0 * corr0 + rs0;
        l1 = l1 * corr1 + rs1;
#pragma unroll
        for (int nt = 0; nt < 4; nt++) {
            o[nt][0] *= corr0; o[nt][1] *= corr0;
            o[nt][2] *= corr1; o[nt][3] *= corr1;
        }

        // ---- O += P @ V (tf32): C-frag is the A-frag after rename, 0 shuffles
#pragma unroll
        for (int grp = 0; grp < 8; grp++) {
            uint32_t pa[4];
            pa[0] = f2tf(s[grp][0]);   // P(r,   grp*8+q)
            pa[1] = f2tf(s[grp][2]);   // P(r+8, grp*8+q)
            pa[2] = f2tf(s[grp][1]);   // P(r,   grp*8+q+4)
            pa[3] = f2tf(s[grp][3]);   // P(r+8, grp*8+q+4)
#pragma unroll
            for (int nt = 0; nt < 4; nt++) {
                uint2 bf = *(const uint2*)&Vtp[grp][q][2 * (nt * 8 + r)];
                uint32_t bb[2] = {bf.x, bf.y};
                mma_tf32(o[nt], pa, bb, o[nt]);
            }
        }
    }

    // epilogue: O /= l, write [b][c][n]
    float inv0 = 1.0f / l0, inv1 = 1.0f / l1;
    const int gr0 = q0 + wid * 16 + r;
    const int gr1 = gr0 + 8;
#pragma unroll
    for (int nt = 0; nt < 4; nt++) {
        int d = nt * 8 + 2 * q;
        float* base = g_o + (bh * HD + d) * NN;
        base[gr0]      = o[nt][0] * inv0;
        base[NN + gr0] = o[nt][1] * inv0;
        base[gr1]      = o[nt][2] * inv1;
        base[NN + gr1] = o[nt][3] * inv1;
    }
}

// ---------------------------------------------------------------------------
// Kernel 4: output projection GEMM (tf32 tensor cores), ld=272.
// ---------------------------------------------------------------------------
__global__ __launch_bounds__(256, 2) void proj_tc_kernel(
    const float* __restrict__ W, const float* __restrict__ bias,
    float* __restrict__ out) {
    __shared__ __align__(16) uint32_t Ap[4][4][272];
    __shared__ __align__(16) uint32_t Bp[4][4][272];
    const int b  = blockIdx.z;
    const int o0 = blockIdx.y * 128;
    const int n0 = blockIdx.x * 128;
    const int tid = threadIdx.x, wid = tid >> 5, lane = tid & 31;
    const int r = lane >> 2, q = lane & 3;
    const int wr = wid >> 2, wc = wid & 3;

    float acc[4][4][4];
#pragma unroll
    for (int mt = 0; mt < 4; mt++)
#pragma unroll
        for (int nt = 0; nt < 4; nt++)
#pragma unroll
            for (int j = 0; j < 4; j++) acc[mt][nt][j] = 0.f;

    for (int k0 = 0; k0 < Cc; k0 += 32) {
        __syncthreads();
#pragma unroll
        for (int it = 0; it < 4; it++) {
            int idx = tid + 256 * it;
            int row = idx >> 3, c4 = idx & 7;
            float4 w4 = *(const float4*)&W[(size_t)(o0 + row) * Cc + k0 + c4 * 4];
            float wv[4] = {w4.x, w4.y, w4.z, w4.w};
#pragma unroll
            for (int j = 0; j < 4; j++) {
                int k = c4 * 4 + j, i = k & 7;
                Ap[k >> 3][i & 3][2 * row + (i >> 2)] = f2tf(wv[j]);
            }
        }
#pragma unroll
        for (int it = 0; it < 16; it++) {
            int idx = tid + 256 * it;
            int c = idx >> 7, n = idx & 127;
            float v = g_o[((size_t)b * Cc + k0 + c) * NN + n0 + n];
            int i = c & 7;
            Bp[c >> 3][i & 3][2 * n + (i >> 2)] = f2tf(v);
        }
        __syncthreads();

#pragma unroll
        for (int kt = 0; kt < 4; kt++) {
            uint32_t af[4][4];
#pragma unroll
            for (int mt = 0; mt < 4; mt++) {
                int m = wr * 64 + mt * 16;
                uint2 lo = *(const uint2*)&Ap[kt][q][2 * (m + r)];
                uint2 hi = *(const uint2*)&Ap[kt][q][2 * (m + 8 + r)];
                af[mt][0] = lo.x; af[mt][1] = hi.x; af[mt][2] = lo.y; af[mt][3] = hi.y;
            }
            uint2 bfv[4];
#pragma unroll
            for (int nt = 0; nt < 4; nt++)
                bfv[nt] = *(const uint2*)&Bp[kt][q][2 * (wc * 32 + nt * 8 + r)];
#pragma unroll
            for (int mt = 0; mt < 4; mt++)
#pragma unroll
                for (int nt = 0; nt < 4; nt++) {
                    uint32_t bb[2] = {bfv[nt].x, bfv[nt].y};
                    mma_tf32(acc[mt][nt], af[mt], bb, acc[mt][nt]);
                }
        }
    }

#pragma unroll
    for (int mt = 0; mt < 4; mt++) {
        int row0 = o0 + wr * 64 + mt * 16 + r;
        int row1 = row0 + 8;
        float bi0 = bias[row0], bi1 = bias[row1];
        float* p0 = out + ((size_t)b * Cc + row0) * NN;
        float* p1 = out + ((size_t)b * Cc + row1) * NN;
#pragma unroll
        for (int nt = 0; nt < 4; nt++) {
            int n = n0 + wc * 32 + nt * 8 + 2 * q;
            float2 v0 = make_float2(acc[mt][nt][0] + bi0, acc[mt][nt][1] + bi0);
            float2 v1 = make_float2(acc[mt][nt][2] + bi1, acc[mt][nt][3] + bi1);
            *(float2*)&p0[n] = v0;
            *(float2*)&p1[n] = v1;
        }
    }
}

// ---------------------------------------------------------------------------
// Launch
// ---------------------------------------------------------------------------
extern "C" void kernel_launch(void* const* d_in, const int* in_sizes, int n_in,
                              void* d_out, int out_size) {
    const float* x    = (const float*)d_in[0];
    const float* gnw  = (const float*)d_in[1];
    const float* gnb  = (const float*)d_in[2];
    const float* wqkv = (const float*)d_in[3];
    const float* bqkv = (const float*)d_in[4];
    const float* wproj= (const float*)d_in[5];
    const float* bproj= (const float*)d_in[6];
    float* out = (float*)d_out;

    gn_stats_partial<<<128, 256>>>(x);
    gn_stats_final<<<1, 16>>>();

    dim3 gq(NN / 128, (3 * Cc) / 128, Bz);
    qkv_tc_kernel<<<gq, 256>>>(x, gnw, gnb, wqkv, bqkv);

    dim3 ga(NN / 128, NH, Bz);
    attn_tc_kernel<<<ga, 256>>>();

    dim3 gp(NN / 128, Cc / 128, Bz);
    proj_tc_kernel<<<gp, 256>>>(wproj, bproj, out);
}

// round 5
// speedup vs baseline: 3.3353x; 1.2742x over previous
#include <cuda_runtime.h>
#include <math.h>
#include <stdint.h>

// ---------------------------------------------------------------------------
// Problem constants
// ---------------------------------------------------------------------------
#define Bz   2
#define Cc   256
#define NH   8
#define HD   32
#define NN   4096
#define CPG  32
#define EPSV 1e-5f
#define LOG2E 1.4426950408889634f

// ---------------------------------------------------------------------------
// Scratch (device globals — no allocation allowed)
// ---------------------------------------------------------------------------
__device__ float g_psum[128];
__device__ float g_psq[128];
__device__ float g_mean[16];
__device__ float g_rstd[16];
__device__ float g_q[Bz * NH * NN * HD];   // [b][h][n][d]
__device__ float g_k[Bz * NH * NN * HD];
__device__ float g_v[Bz * NH * NN * HD];
__device__ float g_o[Bz * Cc * NN];        // [b][c][n]

// ---------------------------------------------------------------------------
// Helpers
// ---------------------------------------------------------------------------
__device__ __forceinline__ uint32_t f2tf(float x) {
    uint32_t r;
    asm("cvt.rna.tf32.f32 %0, %1;" : "=r"(r) : "f"(x));
    return r;
}
__device__ __forceinline__ float ex2f(float x) {
    float r;
    asm("ex2.approx.f32 %0, %1;" : "=f"(r) : "f"(x));
    return r;
}
__device__ __forceinline__ void mma_tf32(float d[4], const uint32_t a[4],
                                         const uint32_t b[2], const float c[4]) {
    asm volatile(
        "mma.sync.aligned.m16n8k8.row.col.f32.tf32.tf32.f32 "
        "{%0,%1,%2,%3}, {%4,%5,%6,%7}, {%8,%9}, {%10,%11,%12,%13};"
        : "=f"(d[0]), "=f"(d[1]), "=f"(d[2]), "=f"(d[3])
        : "r"(a[0]), "r"(a[1]), "r"(a[2]), "r"(a[3]),
          "r"(b[0]), "r"(b[1]),
          "f"(c[0]), "f"(c[1]), "f"(c[2]), "f"(c[3]));
}

// ---------------------------------------------------------------------------
// Kernel 1: GroupNorm stats
// ---------------------------------------------------------------------------
__global__ __launch_bounds__(256) void gn_stats_partial(const float* __restrict__ x) {
    int blk  = blockIdx.x;
    int bg   = blk >> 3;
    int part = blk & 7;
    const float4* p4 = (const float4*)(x + (size_t)bg * CPG * NN + (size_t)part * (CPG * NN / 8));
    const int n4 = (CPG * NN / 8) / 4;
    float s = 0.f, sq = 0.f;
    for (int i = threadIdx.x; i < n4; i += 256) {
        float4 v = p4[i];
        s  += v.x + v.y + v.z + v.w;
        sq += v.x * v.x + v.y * v.y + v.z * v.z + v.w * v.w;
    }
    __shared__ float ss[8], ssq[8];
    for (int o = 16; o; o >>= 1) {
        s  += __shfl_xor_sync(0xffffffffu, s,  o);
        sq += __shfl_xor_sync(0xffffffffu, sq, o);
    }
    if ((threadIdx.x & 31) == 0) { ss[threadIdx.x >> 5] = s; ssq[threadIdx.x >> 5] = sq; }
    __syncthreads();
    if (threadIdx.x == 0) {
        float S = 0.f, SQ = 0.f;
        for (int i = 0; i < 8; i++) { S += ss[i]; SQ += ssq[i]; }
        g_psum[blk] = S;
        g_psq[blk]  = SQ;
    }
}

__global__ void gn_stats_final() {
    int bg = threadIdx.x;
    if (bg >= 16) return;
    float S = 0.f, SQ = 0.f;
    for (int i = 0; i < 8; i++) { S += g_psum[bg * 8 + i]; SQ += g_psq[bg * 8 + i]; }
    const float inv = 1.0f / (float)(CPG * NN);
    float mean = S * inv;
    float var  = SQ * inv - mean * mean;
    g_mean[bg] = mean;
    g_rstd[bg] = rsqrtf(var + EPSV);
}

// ---------------------------------------------------------------------------
// Kernel 2: QKV GEMM (tf32 tensor cores), GroupNorm fused on B load.
// ---------------------------------------------------------------------------
__global__ __launch_bounds__(256, 2) void qkv_tc_kernel(
    const float* __restrict__ x, const float* __restrict__ gnw,
    const float* __restrict__ gnb, const float* __restrict__ W,
    const float* __restrict__ bias) {
    __shared__ __align__(16) uint32_t Ap[4][4][272];
    __shared__ __align__(16) uint32_t Bp[4][4][272];
    const int b  = blockIdx.z;
    const int o0 = blockIdx.y * 128;
    const int n0 = blockIdx.x * 128;
    const int tid = threadIdx.x, wid = tid >> 5, lane = tid & 31;
    const int r = lane >> 2, q = lane & 3;
    const int wr = wid >> 2, wc = wid & 3;

    float acc[4][4][4];
#pragma unroll
    for (int mt = 0; mt < 4; mt++)
#pragma unroll
        for (int nt = 0; nt < 4; nt++)
#pragma unroll
            for (int j = 0; j < 4; j++) acc[mt][nt][j] = 0.f;

    for (int k0 = 0; k0 < Cc; k0 += 32) {
        __syncthreads();
#pragma unroll
        for (int it = 0; it < 4; it++) {
            int idx = tid + 256 * it;
            int row = idx >> 3, c4 = idx & 7;
            float4 w4 = *(const float4*)&W[(size_t)(o0 + row) * Cc + k0 + c4 * 4];
            float wv[4] = {w4.x, w4.y, w4.z, w4.w};
#pragma unroll
            for (int j = 0; j < 4; j++) {
                int k = c4 * 4 + j, i = k & 7;
                Ap[k >> 3][i & 3][2 * row + (i >> 2)] = f2tf(wv[j]);
            }
        }
        const float mu  = g_mean[b * 8 + (k0 >> 5)];
        const float rsd = g_rstd[b * 8 + (k0 >> 5)];
#pragma unroll
        for (int it = 0; it < 16; it++) {
            int idx = tid + 256 * it;
            int c = idx >> 7, n = idx & 127;
            int ch = k0 + c;
            float v = x[((size_t)b * Cc + ch) * NN + n0 + n];
            v = (v - mu) * rsd * gnw[ch] + gnb[ch];
            int i = c & 7;
            Bp[c >> 3][i & 3][2 * n + (i >> 2)] = f2tf(v);
        }
        __syncthreads();

#pragma unroll
        for (int kt = 0; kt < 4; kt++) {
            uint32_t af[4][4];
#pragma unroll
            for (int mt = 0; mt < 4; mt++) {
                int m = wr * 64 + mt * 16;
                uint2 lo = *(const uint2*)&Ap[kt][q][2 * (m + r)];
                uint2 hi = *(const uint2*)&Ap[kt][q][2 * (m + 8 + r)];
                af[mt][0] = lo.x; af[mt][1] = hi.x; af[mt][2] = lo.y; af[mt][3] = hi.y;
            }
            uint2 bfv[4];
#pragma unroll
            for (int nt = 0; nt < 4; nt++)
                bfv[nt] = *(const uint2*)&Bp[kt][q][2 * (wc * 32 + nt * 8 + r)];
#pragma unroll
            for (int mt = 0; mt < 4; mt++)
#pragma unroll
                for (int nt = 0; nt < 4; nt++) {
                    uint32_t bb[2] = {bfv[nt].x, bfv[nt].y};
                    mma_tf32(acc[mt][nt], af[mt], bb, acc[mt][nt]);
                }
        }
    }

#pragma unroll
    for (int mt = 0; mt < 4; mt++) {
        int row0 = o0 + wr * 64 + mt * 16 + r;
        int row1 = row0 + 8;
        float bi0 = bias[row0], bi1 = bias[row1];
        int which = row0 >> 8;
        float* dst = (which == 0) ? g_q : (which == 1 ? g_k : g_v);
        int rem = row0 & 255;
        int hh = rem >> 5;
        int dd0 = rem & 31, dd1 = dd0 + 8;
        float* base = dst + ((size_t)b * NH + hh) * NN * HD;
#pragma unroll
        for (int nt = 0; nt < 4; nt++) {
            int n = n0 + wc * 32 + nt * 8 + 2 * q;
            base[(size_t)n * HD + dd0]       = acc[mt][nt][0] + bi0;
            base[(size_t)(n + 1) * HD + dd0] = acc[mt][nt][1] + bi0;
            base[(size_t)n * HD + dd1]       = acc[mt][nt][2] + bi1;
            base[(size_t)(n + 1) * HD + dd1] = acc[mt][nt][3] + bi1;
        }
    }
}

// ---------------------------------------------------------------------------
// Kernel 3: flash attention, all-tf32, 4 warps x 32 query rows (2 m-tiles).
// Every K/V B-fragment LDS64 is reused by BOTH m-tiles -> LDS bytes/FLOP
// halved vs round 4. Permuted K columns keep PV shuffle-free (S C-frag is
// the PV A-frag after register rename). V staging: lane carries the dim
// index -> contiguous 256B STS64 AND coalesced LDG.
// ---------------------------------------------------------------------------
__global__ __launch_bounds__(128, 2) void attn_tc_kernel() {
    __shared__ __align__(16) uint32_t Ktp[4][4][144];  // [kt][q][2*col+half]
    __shared__ __align__(16) uint32_t Vtp[8][4][80];   // [grp][qi][2*dim+half]

    const int b  = blockIdx.z;
    const int h  = blockIdx.y;
    const int q0 = blockIdx.x * 128;
    const int tid = threadIdx.x, wid = tid >> 5, lane = tid & 31;
    const int r = lane >> 2, q = lane & 3;
    const size_t bh = (size_t)b * NH + h;
    const float sc2 = 0.17677669529663687f * LOG2E;  // 1/sqrt(32) * log2(e)

    // Q fragments: 2 m-tiles of 16 rows, pre-scaled tf32, register resident
    uint32_t qa[2][4][4];
#pragma unroll
    for (int mt = 0; mt < 2; mt++) {
        const float* qg = g_q + (bh * NN + q0 + (size_t)(wid * 32 + mt * 16)) * HD;
#pragma unroll
        for (int kt = 0; kt < 4; kt++) {
            qa[mt][kt][0] = f2tf(qg[(size_t)r       * HD + kt * 8 + q]     * sc2);
            qa[mt][kt][1] = f2tf(qg[(size_t)(r + 8) * HD + kt * 8 + q]     * sc2);
            qa[mt][kt][2] = f2tf(qg[(size_t)r       * HD + kt * 8 + q + 4] * sc2);
            qa[mt][kt][3] = f2tf(qg[(size_t)(r + 8) * HD + kt * 8 + q + 4] * sc2);
        }
    }

    float o[2][4][4];
#pragma unroll
    for (int mt = 0; mt < 2; mt++)
#pragma unroll
        for (int i = 0; i < 4; i++)
#pragma unroll
            for (int j = 0; j < 4; j++) o[mt][i][j] = 0.f;
    float mx[2][2] = {{-1e30f, -1e30f}, {-1e30f, -1e30f}};
    float lsum[2][2] = {{0.f, 0.f}, {0.f, 0.f}};

    // --- staging maps ---
    // K: thread -> key key_ld (0..63), dim half dh (16 dims each)
    const int key_ld = tid >> 1, dh = tid & 1;
    const int kkk = key_ld & 7;
    const int pcol = (key_ld & ~7) + ((kkk < 4) ? 2 * kkk : 2 * kkk - 7);
    // V: lane carries dim (0..31); per iteration i: slot = i*4 + wid -> (grp,qi)
    const int dl = lane;

    const float* kg = g_k + bh * NN * HD;
    const float* vg = g_v + bh * NN * HD;

    float4 kpre[4];
    float vpre[16];
#pragma unroll
    for (int j2 = 0; j2 < 4; j2++)
        kpre[j2] = *(const float4*)&kg[(size_t)key_ld * HD + dh * 16 + j2 * 4];
#pragma unroll
    for (int i = 0; i < 8; i++) {
        int slot = i * 4 + wid;
        int k0 = (slot >> 2) * 8 + (slot & 3);
        vpre[2 * i]     = vg[(size_t)k0 * HD + dl];
        vpre[2 * i + 1] = vg[(size_t)(k0 + 4) * HD + dl];
    }

#pragma unroll 1
    for (int t = 0; t < NN / 64; t++) {
        __syncthreads();
        // stage K: pairs along dim (qq, qq+4), permuted column; STS64
        {
            float kv[16] = {kpre[0].x, kpre[0].y, kpre[0].z, kpre[0].w,
                            kpre[1].x, kpre[1].y, kpre[1].z, kpre[1].w,
                            kpre[2].x, kpre[2].y, kpre[2].z, kpre[2].w,
                            kpre[3].x, kpre[3].y, kpre[3].z, kpre[3].w};
#pragma unroll
            for (int kt2 = 0; kt2 < 2; kt2++)
#pragma unroll
                for (int qq = 0; qq < 4; qq++) {
                    uint2 w = make_uint2(f2tf(kv[kt2 * 8 + qq]),
                                         f2tf(kv[kt2 * 8 + qq + 4]));
                    *(uint2*)&Ktp[dh * 2 + kt2][qq][2 * pcol] = w;
                }
            // stage V: pairs along keys (qi, qi+4); contiguous STS64
#pragma unroll
            for (int i = 0; i < 8; i++) {
                int slot = i * 4 + wid;
                uint2 w = make_uint2(f2tf(vpre[2 * i]), f2tf(vpre[2 * i + 1]));
                *(uint2*)&Vtp[slot >> 2][slot & 3][2 * dl] = w;
            }
        }
        __syncthreads();

        if (t + 1 < NN / 64) {
            const float* kg2 = kg + (size_t)(t + 1) * 64 * HD;
            const float* vg2 = vg + (size_t)(t + 1) * 64 * HD;
#pragma unroll
            for (int j2 = 0; j2 < 4; j2++)
                kpre[j2] = *(const float4*)&kg2[(size_t)key_ld * HD + dh * 16 + j2 * 4];
#pragma unroll
            for (int i = 0; i < 8; i++) {
                int slot = i * 4 + wid;
                int k0 = (slot >> 2) * 8 + (slot & 3);
                vpre[2 * i]     = vg2[(size_t)k0 * HD + dl];
                vpre[2 * i + 1] = vg2[(size_t)(k0 + 4) * HD + dl];
            }
        }

        // ---- S = Q K^T (tf32): each B-frag LDS64 feeds 2 m-tiles ----
        float s[2][8][4];
#pragma unroll
        for (int nt = 0; nt < 8; nt++) {
            s[0][nt][0] = s[0][nt][1] = s[0][nt][2] = s[0][nt][3] = 0.f;
            s[1][nt][0] = s[1][nt][1] = s[1][nt][2] = s[1][nt][3] = 0.f;
#pragma unroll
            for (int kt = 0; kt < 4; kt++) {
                uint2 bf = *(const uint2*)&Ktp[kt][q][2 * (nt * 8 + r)];
                uint32_t bb[2] = {bf.x, bf.y};
                mma_tf32(s[0][nt], qa[0][kt], bb, s[0][nt]);
                mma_tf32(s[1][nt], qa[1][kt], bb, s[1][nt]);
            }
        }

        // ---- online softmax (base 2), per m-tile ----
#pragma unroll
        for (int mt = 0; mt < 2; mt++) {
            float rm0 = -1e30f, rm1 = -1e30f;
#pragma unroll
            for (int nt = 0; nt < 8; nt++) {
                rm0 = fmaxf(rm0, fmaxf(s[mt][nt][0], s[mt][nt][1]));
                rm1 = fmaxf(rm1, fmaxf(s[mt][nt][2], s[mt][nt][3]));
            }
            rm0 = fmaxf(rm0, __shfl_xor_sync(0xffffffffu, rm0, 1));
            rm0 = fmaxf(rm0, __shfl_xor_sync(0xffffffffu, rm0, 2));
            rm1 = fmaxf(rm1, __shfl_xor_sync(0xffffffffu, rm1, 1));
            rm1 = fmaxf(rm1, __shfl_xor_sync(0xffffffffu, rm1, 2));
            float mn0 = fmaxf(mx[mt][0], rm0), mn1 = fmaxf(mx[mt][1], rm1);
            float corr0 = ex2f(mx[mt][0] - mn0), corr1 = ex2f(mx[mt][1] - mn1);
            mx[mt][0] = mn0; mx[mt][1] = mn1;
            float rs0 = 0.f, rs1 = 0.f;
#pragma unroll
            for (int nt = 0; nt < 8; nt++) {
                s[mt][nt][0] = ex2f(s[mt][nt][0] - mn0); rs0 += s[mt][nt][0];
                s[mt][nt][1] = ex2f(s[mt][nt][1] - mn0); rs0 += s[mt][nt][1];
                s[mt][nt][2] = ex2f(s[mt][nt][2] - mn1); rs1 += s[mt][nt][2];
                s[mt][nt][3] = ex2f(s[mt][nt][3] - mn1); rs1 += s[mt][nt][3];
            }
            rs0 += __shfl_xor_sync(0xffffffffu, rs0, 1);
            rs0 += __shfl_xor_sync(0xffffffffu, rs0, 2);
            rs1 += __shfl_xor_sync(0xffffffffu, rs1, 1);
            rs1 += __shfl_xor_sync(0xffffffffu, rs1, 2);
            lsum[mt][0] = lsum[mt][0] * corr0 + rs0;
            lsum[mt][1] = lsum[mt][1] * corr1 + rs1;
#pragma unroll
            for (int nt = 0; nt < 4; nt++) {
                o[mt][nt][0] *= corr0; o[mt][nt][1] *= corr0;
                o[mt][nt][2] *= corr1; o[mt][nt][3] *= corr1;
            }
        }

        // ---- O += P @ V: C-frag==A-frag (rename), V B-frag reused 2x ----
#pragma unroll
        for (int grp = 0; grp < 8; grp++) {
            uint32_t pa[2][4];
#pragma unroll
            for (int mt = 0; mt < 2; mt++) {
                pa[mt][0] = f2tf(s[mt][grp][0]);
                pa[mt][1] = f2tf(s[mt][grp][2]);
                pa[mt][2] = f2tf(s[mt][grp][1]);
                pa[mt][3] = f2tf(s[mt][grp][3]);
            }
#pragma unroll
            for (int nt = 0; nt < 4; nt++) {
                uint2 bf = *(const uint2*)&Vtp[grp][q][2 * (nt * 8 + r)];
                uint32_t bb[2] = {bf.x, bf.y};
                mma_tf32(o[0][nt], pa[0], bb, o[0][nt]);
                mma_tf32(o[1][nt], pa[1], bb, o[1][nt]);
            }
        }
    }

    // epilogue: O /= l, write [b][c][n]
#pragma unroll
    for (int mt = 0; mt < 2; mt++) {
        float inv0 = 1.0f / lsum[mt][0], inv1 = 1.0f / lsum[mt][1];
        const int gr0 = q0 + wid * 32 + mt * 16 + r;
        const int gr1 = gr0 + 8;
#pragma unroll
        for (int nt = 0; nt < 4; nt++) {
            int d = nt * 8 + 2 * q;
            float* base = g_o + (bh * HD + d) * NN;
            base[gr0]      = o[mt][nt][0] * inv0;
            base[NN + gr0] = o[mt][nt][1] * inv0;
            base[gr1]      = o[mt][nt][2] * inv1;
            base[NN + gr1] = o[mt][nt][3] * inv1;
        }
    }
}

// ---------------------------------------------------------------------------
// Kernel 4: output projection GEMM (tf32 tensor cores).
// ---------------------------------------------------------------------------
__global__ __launch_bounds__(256, 2) void proj_tc_kernel(
    const float* __restrict__ W, const float* __restrict__ bias,
    float* __restrict__ out) {
    __shared__ __align__(16) uint32_t Ap[4][4][272];
    __shared__ __align__(16) uint32_t Bp[4][4][272];
    const int b  = blockIdx.z;
    const int o0 = blockIdx.y * 128;
    const int n0 = blockIdx.x * 128;
    const int tid = threadIdx.x, wid = tid >> 5, lane = tid & 31;
    const int r = lane >> 2, q = lane & 3;
    const int wr = wid >> 2, wc = wid & 3;

    float acc[4][4][4];
#pragma unroll
    for (int mt = 0; mt < 4; mt++)
#pragma unroll
        for (int nt = 0; nt < 4; nt++)
#pragma unroll
            for (int j = 0; j < 4; j++) acc[mt][nt][j] = 0.f;

    for (int k0 = 0; k0 < Cc; k0 += 32) {
        __syncthreads();
#pragma unroll
        for (int it = 0; it < 4; it++) {
            int idx = tid + 256 * it;
            int row = idx >> 3, c4 = idx & 7;
            float4 w4 = *(const float4*)&W[(size_t)(o0 + row) * Cc + k0 + c4 * 4];
            float wv[4] = {w4.x, w4.y, w4.z, w4.w};
#pragma unroll
            for (int j = 0; j < 4; j++) {
                int k = c4 * 4 + j, i = k & 7;
                Ap[k >> 3][i & 3][2 * row + (i >> 2)] = f2tf(wv[j]);
            }
        }
#pragma unroll
        for (int it = 0; it < 16; it++) {
            int idx = tid + 256 * it;
            int c = idx >> 7, n = idx & 127;
            float v = g_o[((size_t)b * Cc + k0 + c) * NN + n0 + n];
            int i = c & 7;
            Bp[c >> 3][i & 3][2 * n + (i >> 2)] = f2tf(v);
        }
        __syncthreads();

#pragma unroll
        for (int kt = 0; kt < 4; kt++) {
            uint32_t af[4][4];
#pragma unroll
            for (int mt = 0; mt < 4; mt++) {
                int m = wr * 64 + mt * 16;
                uint2 lo = *(const uint2*)&Ap[kt][q][2 * (m + r)];
                uint2 hi = *(const uint2*)&Ap[kt][q][2 * (m + 8 + r)];
                af[mt][0] = lo.x; af[mt][1] = hi.x; af[mt][2] = lo.y; af[mt][3] = hi.y;
            }
            uint2 bfv[4];
#pragma unroll
            for (int nt = 0; nt < 4; nt++)
                bfv[nt] = *(const uint2*)&Bp[kt][q][2 * (wc * 32 + nt * 8 + r)];
#pragma unroll
            for (int mt = 0; mt < 4; mt++)
#pragma unroll
                for (int nt = 0; nt < 4; nt++) {
                    uint32_t bb[2] = {bfv[nt].x, bfv[nt].y};
                    mma_tf32(acc[mt][nt], af[mt], bb, acc[mt][nt]);
                }
        }
    }

#pragma unroll
    for (int mt = 0; mt < 4; mt++) {
        int row0 = o0 + wr * 64 + mt * 16 + r;
        int row1 = row0 + 8;
        float bi0 = bias[row0], bi1 = bias[row1];
        float* p0 = out + ((size_t)b * Cc + row0) * NN;
        float* p1 = out + ((size_t)b * Cc + row1) * NN;
#pragma unroll
        for (int nt = 0; nt < 4; nt++) {
            int n = n0 + wc * 32 + nt * 8 + 2 * q;
            float2 v0 = make_float2(acc[mt][nt][0] + bi0, acc[mt][nt][1] + bi0);
            float2 v1 = make_float2(acc[mt][nt][2] + bi1, acc[mt][nt][3] + bi1);
            *(float2*)&p0[n] = v0;
            *(float2*)&p1[n] = v1;
        }
    }
}

// ---------------------------------------------------------------------------
// Launch
// ---------------------------------------------------------------------------
extern "C" void kernel_launch(void* const* d_in, const int* in_sizes, int n_in,
                              void* d_out, int out_size) {
    const float* x    = (const float*)d_in[0];
    const float* gnw  = (const float*)d_in[1];
    const float* gnb  = (const float*)d_in[2];
    const float* wqkv = (const float*)d_in[3];
    const float* bqkv = (const float*)d_in[4];
    const float* wproj= (const float*)d_in[5];
    const float* bproj= (const float*)d_in[6];
    float* out = (float*)d_out;

    gn_stats_partial<<<128, 256>>>(x);
    gn_stats_final<<<1, 16>>>();

    dim3 gq(NN / 128, (3 * Cc) / 128, Bz);
    qkv_tc_kernel<<<gq, 256>>>(x, gnw, gnb, wqkv, bqkv);

    dim3 ga(NN / 128, NH, Bz);
    attn_tc_kernel<<<ga, 128>>>();

    dim3 gp(NN / 128, Cc / 128, Bz);
    proj_tc_kernel<<<gp, 256>>>(wproj, bproj, out);
}